// round 5
// baseline (speedup 1.0000x reference)
#include <cuda_runtime.h>
#include <mma.h>
#include <math.h>
#include <stdint.h>

using namespace nvcuda;

// Problem constants
#define NB   2
#define NT   2048
#define ND   512
#define NH   8
#define NHD  64
#define NQKV 1536
#define MAXROWS (NB*NT)        // 4096
#define PADROWS (MAXROWS+128)  // slack for tile-store overhang

// ---------------- scratch (device globals; no allocations allowed) ----------
__device__ float d_qkv   [ (size_t)PADROWS*NQKV ];
__device__ float d_S     [ (size_t)NB*NH*NT*NT ];     // raw scores, ld = NT
__device__ float d_AO    [ (size_t)PADROWS*ND ];
__device__ float d_stage [ (size_t)PADROWS*ND ];
__device__ float d_merged[ (size_t)PADROWS*ND ];
__device__ float d_rinv  [ NB*NH*NT ];                // 1 / sum(exp(row))

__device__ int g_ids1[NT];
__device__ int g_ids2[NT];
__device__ int g_start1[NT+2];
__device__ int g_start2[NT+2];
__device__ int g_m1, g_m2, g_ntok;
__device__ int g_tokmap[NT];
__device__ int g_tokg[NT];
__device__ long long g_off[3];   // [0]=char_w off, [1]=block_w off, [2]=glob_w off

__device__ __forceinline__ int seqlen(int stage) {
    return stage == 0 ? NT : (stage == 1 ? g_m1 : g_m2);
}

// ---------------- setup: ids / starts / token map / offsets -----------------
__global__ void setup_kernel(const float* __restrict__ mw, const float* __restrict__ mb,
                             const float* __restrict__ gw, const float* __restrict__ gb) {
    if (threadIdx.x != 0 || blockIdx.x != 0) return;

    double s = 0.0;
    for (int i = 0; i < ND; i++) s += (double)mw[i];
    float c1 = (float)s + mb[0];
    s = 0.0;
    for (int i = 0; i < ND; i++) s += (double)gw[i];
    float c2 = (float)s + gb[0];

    float cum = 0.f, last = 0.f;
    for (int i = 0; i < NT; i++) { cum += c1; last = cum - floorf(cum); }
    cum = 0.f; float prev = last; int id = 0;
    for (int i = 0; i < NT; i++) {
        cum += c1;
        float fr = cum - floorf(cum);
        if (fr < prev) id++;
        g_ids1[i] = id;
        prev = fr;
    }
    int m1 = id;
    g_m1 = m1;
    {
        int prevId = 0;
        for (int i = 0; i < NT; i++) {
            int v = g_ids1[i];
            if (v > prevId) { for (int j = prevId + 1; j <= v; j++) g_start1[j] = i; prevId = v; }
        }
        g_start1[m1 + 1] = NT;
    }

    cum = 0.f; last = 0.f;
    for (int i = 0; i < m1; i++) { cum += c2; last = cum - floorf(cum); }
    cum = 0.f; prev = last; id = 0;
    for (int i = 0; i < m1; i++) {
        cum += c2;
        float fr = cum - floorf(cum);
        if (fr < prev) id++;
        g_ids2[i] = id;
        prev = fr;
    }
    int m2 = id;
    g_m2 = m2;
    {
        int prevId = 0;
        for (int i = 0; i < m1; i++) {
            int v = g_ids2[i];
            if (v > prevId) { for (int j = prevId + 1; j <= v; j++) g_start2[j] = i; prevId = v; }
        }
        g_start2[m2 + 1] = m1;
    }

    int n = 0;
    for (int t = 0; t < NT; t++) {
        int i1 = g_ids1[t];
        int tg = (i1 >= 1) ? g_ids2[i1 - 1] : 0;
        g_tokg[t] = tg;
        if (tg >= 1) g_tokmap[n++] = t;
    }
    g_ntok = n;

    long long offcw = (long long)NB * n * ND;
    g_off[0] = offcw;
    g_off[1] = offcw + (long long)NB * NT * NT;
    g_off[2] = g_off[1] + (long long)NB * m1 * m1;
}

// =============== 3xTF32 wmma GEMM core =====================================
// C[M,N] = scale * A[M,K] * B
//   BROW=false: B is [N,K] row-major (op = A*B^T)
//   BROW=true : B is [K,N] row-major
//   EXPA: A elements become expf(a)*rinv[row] (attn@V without materializing P)
//   CGUARD: stage result via smem, bounds-check every row/col on global store
//           (needed when C rows beyond M would collide with other data)
template<int BM, int BN, int BK, int WM, int WN, bool BROW, bool EXPA, bool CGUARD>
__device__ __forceinline__ void gemm_core(
    const float* __restrict__ A, int lda,
    const float* __restrict__ B, int ldb,
    float* __restrict__ C, int ldc,
    int M, int N, int K, float scale,
    const float* __restrict__ rinv,
    int m0, int n0)
{
    constexpr int LDS = BK + 4;
    constexpr int LOADSZ = (BM + BN) * LDS;
    constexpr int EPILDS = BN + 4;
    constexpr int EPISZ = CGUARD ? BM * EPILDS : 0;
    constexpr int SMEMSZ = (LOADSZ > EPISZ) ? LOADSZ : EPISZ;
    __shared__ __align__(16) float smem[SMEMSZ];
    float* As = smem;
    float* Bs = smem + BM * LDS;

    const int tid  = threadIdx.x;          // 256 threads
    const int warp = tid >> 5;
    constexpr int WROWS = BM / WM;
    const int wm0 = (warp % WROWS) * WM;
    const int wn0 = (warp / WROWS) * WN;
    constexpr int AM = WM / 16, AN = WN / 16;

    wmma::fragment<wmma::accumulator, 16, 16, 8, float> acc[AM][AN];
    #pragma unroll
    for (int i = 0; i < AM; i++)
        #pragma unroll
        for (int j = 0; j < AN; j++) wmma::fill_fragment(acc[i][j], 0.f);

    for (int k0 = 0; k0 < K; k0 += BK) {
        // ---- load A tile (zero-filled OOB) ----
        for (int i = tid; i < BM * (BK / 4); i += 256) {
            int r = i / (BK / 4), c4 = (i % (BK / 4)) * 4;
            int gr = m0 + r, gk = k0 + c4;
            float4 v = make_float4(0.f, 0.f, 0.f, 0.f);
            bool rowok = (gr < M);
            if (rowok && gk < K)
                v = *(const float4*)(A + (size_t)gr * lda + gk);
            if (EXPA) {
                float ri = rowok ? rinv[gr] : 0.f;
                v.x = (rowok && gk     < K) ? expf(v.x) * ri : 0.f;
                v.y = (rowok && gk + 1 < K) ? expf(v.y) * ri : 0.f;
                v.z = (rowok && gk + 2 < K) ? expf(v.z) * ri : 0.f;
                v.w = (rowok && gk + 3 < K) ? expf(v.w) * ri : 0.f;
            } else {
                if (gk + 1 >= K) v.y = 0.f;
                if (gk + 2 >= K) v.z = 0.f;
                if (gk + 3 >= K) v.w = 0.f;
            }
            *(float4*)&As[r * LDS + c4] = v;
        }
        // ---- load B tile into [n][k] layout ----
        if (!BROW) {
            for (int i = tid; i < BN * (BK / 4); i += 256) {
                int r = i / (BK / 4), c4 = (i % (BK / 4)) * 4;
                int gn = n0 + r, gk = k0 + c4;
                float4 v = make_float4(0.f, 0.f, 0.f, 0.f);
                if (gn < N && gk < K)
                    v = *(const float4*)(B + (size_t)gn * ldb + gk);
                if (gk + 1 >= K) v.y = 0.f;
                if (gk + 2 >= K) v.z = 0.f;
                if (gk + 3 >= K) v.w = 0.f;
                *(float4*)&Bs[r * LDS + c4] = v;
            }
        } else {
            for (int i = tid; i < BK * (BN / 4); i += 256) {
                int kr = i / (BN / 4), c4 = (i % (BN / 4)) * 4;
                int gk = k0 + kr, gn = n0 + c4;
                float4 v = make_float4(0.f, 0.f, 0.f, 0.f);
                if (gk < K && gn < N)
                    v = *(const float4*)(B + (size_t)gk * ldb + gn);
                Bs[(c4 + 0) * LDS + kr] = v.x;
                Bs[(c4 + 1) * LDS + kr] = v.y;
                Bs[(c4 + 2) * LDS + kr] = v.z;
                Bs[(c4 + 3) * LDS + kr] = v.w;
            }
        }
        __syncthreads();

        #pragma unroll
        for (int kk = 0; kk < BK; kk += 8) {
            wmma::fragment<wmma::matrix_a, 16, 16, 8, wmma::precision::tf32, wmma::row_major> ah[AM], al[AM];
            #pragma unroll
            for (int i = 0; i < AM; i++) {
                wmma::load_matrix_sync(ah[i], &As[(wm0 + i * 16) * LDS + kk], LDS);
                #pragma unroll
                for (int e = 0; e < ah[i].num_elements; e++) {
                    float v = ah[i].x[e];
                    float h = wmma::__float_to_tf32(v);
                    ah[i].x[e] = h;
                    al[i].x[e] = wmma::__float_to_tf32(v - h);
                }
            }
            #pragma unroll
            for (int j = 0; j < AN; j++) {
                wmma::fragment<wmma::matrix_b, 16, 16, 8, wmma::precision::tf32, wmma::col_major> bh, bl;
                wmma::load_matrix_sync(bh, &Bs[(wn0 + j * 16) * LDS + kk], LDS);
                #pragma unroll
                for (int e = 0; e < bh.num_elements; e++) {
                    float v = bh.x[e];
                    float h = wmma::__float_to_tf32(v);
                    bh.x[e] = h;
                    bl.x[e] = wmma::__float_to_tf32(v - h);
                }
                #pragma unroll
                for (int i = 0; i < AM; i++) {
                    wmma::mma_sync(acc[i][j], ah[i], bh, acc[i][j]);
                    wmma::mma_sync(acc[i][j], al[i], bh, acc[i][j]);
                    wmma::mma_sync(acc[i][j], ah[i], bl, acc[i][j]);
                }
            }
        }
        __syncthreads();
    }

    #pragma unroll
    for (int i = 0; i < AM; i++)
        #pragma unroll
        for (int j = 0; j < AN; j++) {
            #pragma unroll
            for (int e = 0; e < acc[i][j].num_elements; e++) acc[i][j].x[e] *= scale;
        }

    if (!CGUARD) {
        #pragma unroll
        for (int i = 0; i < AM; i++)
            #pragma unroll
            for (int j = 0; j < AN; j++)
                wmma::store_matrix_sync(C + (size_t)(m0 + wm0 + i * 16) * ldc + (n0 + wn0 + j * 16),
                                        acc[i][j], ldc, wmma::mem_row_major);
    } else {
        // stage to smem, then bounds-checked scatter
        #pragma unroll
        for (int i = 0; i < AM; i++)
            #pragma unroll
            for (int j = 0; j < AN; j++)
                wmma::store_matrix_sync(smem + (wm0 + i * 16) * EPILDS + (wn0 + j * 16),
                                        acc[i][j], EPILDS, wmma::mem_row_major);
        __syncthreads();
        for (int idx = tid; idx < BM * BN; idx += 256) {
            int r = idx / BN, c = idx % BN;
            int gr = m0 + r, gc = n0 + c;
            if (gr < M && gc < N)
                C[(size_t)gr * ldc + gc] = smem[r * EPILDS + c];
        }
    }
}

// ---------------- GEMM wrappers ---------------------------------------------
__global__ __launch_bounds__(256, 2)
void k_gemm(const float* __restrict__ Aext, int Asel,
            const float* __restrict__ W, int Csel, int N, int K, int stage) {
    int M = NB * seqlen(stage);
    int m0 = blockIdx.y * 128;
    if (m0 >= M) return;
    int n0 = blockIdx.x * 128;
    const float* A = (Asel == 0) ? Aext : (Asel == 1 ? d_merged : d_AO);
    float* C = (Csel == 0) ? d_qkv : d_stage;
    gemm_core<128, 128, 32, 32, 64, false, false, false>(A, K, W, K, C, N, M, N, K, 1.f, nullptr, m0, n0);
}

__global__ __launch_bounds__(256, 2)
void k_scores(int stage) {
    int L = seqlen(stage);
    int m0 = blockIdx.y * 128, n0 = blockIdx.x * 128;
    if (m0 >= L || n0 >= L) return;
    int bh = blockIdx.z;
    int b = bh / NH, h = bh % NH;
    const float* Q  = d_qkv + (size_t)b * L * NQKV + h * NHD;
    const float* Kp = Q + ND;
    float* S = d_S + (size_t)bh * NT * NT;
    gemm_core<128, 128, 32, 32, 64, false, false, false>(Q, NQKV, Kp, NQKV, S, NT, L, L, NHD, 0.125f, nullptr, m0, n0);
}

__global__ __launch_bounds__(256, 2)
void k_av(int stage) {
    int L = seqlen(stage);
    int m0 = blockIdx.y * 128;
    if (m0 >= L) return;
    int bh = blockIdx.z;
    int b = bh / NH, h = bh % NH;
    const float* S = d_S + (size_t)bh * NT * NT;
    const float* V = d_qkv + (size_t)b * L * NQKV + 2 * ND + h * NHD;
    float* C = d_AO + (size_t)b * L * ND + h * NHD;
    // CGUARD: batch-0 tile overhang must NOT stomp batch-1 rows in d_AO
    gemm_core<128, 64, 32, 32, 32, true, true, true>(S, NT, V, NQKV, C, ND, L, NHD, L, 1.f,
                                                     d_rinv + (size_t)bh * NT, m0, 0);
}

// ---------------- bias add --------------------------------------------------
__global__ __launch_bounds__(256)
void k_bias(int Csel, const float* __restrict__ bias, int N, int stage) {
    int M = NB * seqlen(stage);
    int r = blockIdx.y;
    if (r >= M) return;
    int c = blockIdx.x * 256 + threadIdx.x;
    if (c >= N) return;
    float* C = (Csel == 0) ? d_qkv : d_stage;
    C[(size_t)r * N + c] += bias[c];
}

// ------- fused row stats (sum of exp) + head-mean output --------------------
__global__ __launch_bounds__(256)
void k_rowstat(int stage, float* __restrict__ out) {
    int L = seqlen(stage);
    int q = blockIdx.x;
    if (q >= L) return;
    int b = blockIdx.y;
    int t = threadIdx.x;

    float e[NH][8];
    float rv[NH];
    __shared__ float red[256];

    #pragma unroll
    for (int h = 0; h < NH; h++) {
        const float* row = d_S + ((size_t)(b * NH + h) * NT + q) * NT;
        float s = 0.f;
        #pragma unroll
        for (int c = 0; c < 8; c++) {
            int k = t + (c << 8);
            float x = (k < L) ? expf(row[k]) : 0.f;
            e[h][c] = x;
            s += x;
        }
        red[t] = s; __syncthreads();
        #pragma unroll
        for (int st = 128; st > 0; st >>= 1) { if (t < st) red[t] += red[t + st]; __syncthreads(); }
        rv[h] = 1.f / red[0];
        __syncthreads();
    }

    float* dst = out + g_off[stage] + ((size_t)b * L + q) * L;
    #pragma unroll
    for (int c = 0; c < 8; c++) {
        int k = t + (c << 8);
        if (k < L) {
            float s = 0.f;
            #pragma unroll
            for (int h = 0; h < NH; h++) s += e[h][c] * rv[h];
            dst[k] = 0.125f * s;
        }
    }
    if (t == 0) {
        #pragma unroll
        for (int h = 0; h < NH; h++) d_rinv[(size_t)(b * NH + h) * NT + q] = rv[h];
    }
}

// ---------------- segment mean merge: d_stage -> d_merged -------------------
__global__ __launch_bounds__(256)
void merge_kernel(int which) {
    int m   = (which == 1) ? g_m1 : g_m2;
    int Tin = (which == 1) ? NT : g_m1;
    const int* start = (which == 1) ? g_start1 : g_start2;
    int j = blockIdx.x + 1;
    if (j > m) return;
    int b = blockIdx.y;
    int s0 = start[j], s1 = start[j + 1];
    float cnt = (float)(s1 - s0);
    const float* in = d_stage + ((size_t)b * Tin) * ND;
    float* outp = d_merged + ((size_t)(b * m + (j - 1))) * ND;
    for (int d = threadIdx.x; d < ND; d += 256) {
        float s = 0.f;
        for (int t = s0; t < s1; t++) s += in[(size_t)t * ND + d];
        outp[d] = s / (cnt + 1e-10f);
    }
}

// ---------------- expand glob_out to selected tokens -> d_out[0..] ----------
__global__ __launch_bounds__(256)
void expand_kernel(float* __restrict__ out) {
    int i = blockIdx.x;
    if (i >= g_ntok) return;
    int b = blockIdx.y;
    int t = g_tokmap[i];
    int gsrc = g_tokg[t] - 1;
    int m2 = g_m2;
    const float* src = d_stage + ((size_t)(b * m2 + gsrc)) * ND;
    float* dst = out + ((size_t)b * g_ntok + i) * ND;
    for (int d = threadIdx.x; d < ND; d += 256) dst[d] = src[d];
}

// ---------------- launch ----------------------------------------------------
extern "C" void kernel_launch(void* const* d_in, const int* in_sizes, int n_in,
                              void* d_out, int out_size) {
    (void)in_sizes; (void)n_in; (void)out_size;
    const float* x    = (const float*)d_in[0];
    const float* cWi  = (const float*)d_in[1];
    const float* cbi  = (const float*)d_in[2];
    const float* cWo  = (const float*)d_in[3];
    const float* cbo  = (const float*)d_in[4];
    const float* bWi  = (const float*)d_in[5];
    const float* bbi  = (const float*)d_in[6];
    const float* bWo  = (const float*)d_in[7];
    const float* bbo  = (const float*)d_in[8];
    const float* gWi  = (const float*)d_in[9];
    const float* gbi  = (const float*)d_in[10];
    const float* gWo  = (const float*)d_in[11];
    const float* gbo  = (const float*)d_in[12];
    const float* mw   = (const float*)d_in[13];
    const float* mb   = (const float*)d_in[14];
    const float* gmw  = (const float*)d_in[15];
    const float* gmb  = (const float*)d_in[16];
    float* out = (float*)d_out;

    setup_kernel<<<1, 1>>>(mw, mb, gmw, gmb);

    const dim3 gQKV(NQKV / 128, MAXROWS / 128);   // (12, 32)
    const dim3 gOUT(ND / 128, MAXROWS / 128);     // (4, 32)
    const dim3 gSC(NT / 128, NT / 128, NB * NH);  // (16, 16, 16)
    const dim3 gAV(1, NT / 128, NB * NH);         // (1, 16, 16)
    const dim3 gBQ(NQKV / 256, MAXROWS);          // (6, 4096)
    const dim3 gBO(ND / 256, MAXROWS);            // (2, 4096)
    const dim3 gRS(NT, NB);

    for (int stage = 0; stage < 3; stage++) {
        const float* Wi = stage == 0 ? cWi : (stage == 1 ? bWi : gWi);
        const float* bi = stage == 0 ? cbi : (stage == 1 ? bbi : gbi);
        const float* Wo = stage == 0 ? cWo : (stage == 1 ? bWo : gWo);
        const float* bo = stage == 0 ? cbo : (stage == 1 ? bbo : gbo);
        int Asel = (stage == 0) ? 0 : 1;

        k_gemm<<<gQKV, 256>>>(x, Asel, Wi, 0, NQKV, ND, stage);
        k_bias<<<gBQ, 256>>>(0, bi, NQKV, stage);
        k_scores<<<gSC, 256>>>(stage);
        k_rowstat<<<gRS, 256>>>(stage, out);
        k_av<<<gAV, 256>>>(stage);
        k_gemm<<<gOUT, 256>>>(nullptr, 2, Wo, 1, ND, ND, stage);
        k_bias<<<gBO, 256>>>(1, bo, ND, stage);

        if (stage == 0) merge_kernel<<<dim3(NT, NB), 256>>>(1);
        if (stage == 1) merge_kernel<<<dim3(NT, NB), 256>>>(2);
    }

    expand_kernel<<<dim3(NT, NB), 256>>>(out);
}

// round 6
// speedup vs baseline: 1.0630x; 1.0630x over previous
#include <cuda_runtime.h>
#include <mma.h>
#include <math.h>
#include <stdint.h>

using namespace nvcuda;

// Problem constants
#define NB   2
#define NT   2048
#define ND   512
#define NH   8
#define NHD  64
#define NQKV 1536
#define MAXROWS (NB*NT)        // 4096
#define PADROWS (MAXROWS+128)  // slack for tile-store overhang

// ---------------- scratch (device globals; no allocations allowed) ----------
__device__ float d_qkv   [ (size_t)PADROWS*NQKV ];
__device__ float d_S     [ (size_t)NB*NH*NT*NT ];     // raw scores, ld = NT
__device__ float d_AO    [ (size_t)PADROWS*ND ];
__device__ float d_stage [ (size_t)PADROWS*ND ];
__device__ float d_merged[ (size_t)PADROWS*ND ];
__device__ float d_rinv  [ NB*NH*NT ];                // 1 / sum(exp(row))

__device__ int g_ids1[NT];
__device__ int g_ids2[NT];
__device__ int g_start1[NT+2];
__device__ int g_start2[NT+2];
__device__ int g_m1, g_m2, g_ntok;
__device__ int g_tokmap[NT];
__device__ int g_tokg[NT];
__device__ long long g_off[3];

__device__ __forceinline__ int seqlen(int stage) {
    return stage == 0 ? NT : (stage == 1 ? g_m1 : g_m2);
}

// ---------------- setup: ids / starts / token map / offsets -----------------
__global__ void setup_kernel(const float* __restrict__ mw, const float* __restrict__ mb,
                             const float* __restrict__ gw, const float* __restrict__ gb) {
    if (threadIdx.x != 0 || blockIdx.x != 0) return;

    double s = 0.0;
    for (int i = 0; i < ND; i++) s += (double)mw[i];
    float c1 = (float)s + mb[0];
    s = 0.0;
    for (int i = 0; i < ND; i++) s += (double)gw[i];
    float c2 = (float)s + gb[0];

    float cum = 0.f, last = 0.f;
    for (int i = 0; i < NT; i++) { cum += c1; last = cum - floorf(cum); }
    cum = 0.f; float prev = last; int id = 0;
    for (int i = 0; i < NT; i++) {
        cum += c1;
        float fr = cum - floorf(cum);
        if (fr < prev) id++;
        g_ids1[i] = id;
        prev = fr;
    }
    int m1 = id;
    g_m1 = m1;
    {
        int prevId = 0;
        for (int i = 0; i < NT; i++) {
            int v = g_ids1[i];
            if (v > prevId) { for (int j = prevId + 1; j <= v; j++) g_start1[j] = i; prevId = v; }
        }
        g_start1[m1 + 1] = NT;
    }

    cum = 0.f; last = 0.f;
    for (int i = 0; i < m1; i++) { cum += c2; last = cum - floorf(cum); }
    cum = 0.f; prev = last; id = 0;
    for (int i = 0; i < m1; i++) {
        cum += c2;
        float fr = cum - floorf(cum);
        if (fr < prev) id++;
        g_ids2[i] = id;
        prev = fr;
    }
    int m2 = id;
    g_m2 = m2;
    {
        int prevId = 0;
        for (int i = 0; i < m1; i++) {
            int v = g_ids2[i];
            if (v > prevId) { for (int j = prevId + 1; j <= v; j++) g_start2[j] = i; prevId = v; }
        }
        g_start2[m2 + 1] = m1;
    }

    int n = 0;
    for (int t = 0; t < NT; t++) {
        int i1 = g_ids1[t];
        int tg = (i1 >= 1) ? g_ids2[i1 - 1] : 0;
        g_tokg[t] = tg;
        if (tg >= 1) g_tokmap[n++] = t;
    }
    g_ntok = n;

    long long offcw = (long long)NB * n * ND;
    g_off[0] = offcw;
    g_off[1] = offcw + (long long)NB * NT * NT;
    g_off[2] = g_off[1] + (long long)NB * m1 * m1;
}

// =============== 3xTF32 wmma GEMM core, hi/lo split done in smem ============
// Fixed tiles: BM=128, BN=64, BK=16; 8 warps, warp tile 32x32.
// C[M,N] = scale * A[M,K] * B (+bias)
//   BROW=false: B is [N,K] row-major (op = A*B^T)
//   BROW=true : B is [K,N] row-major
//   EXPA: A elements become expf(a)*rinv[row]
//   DIRECT: store fragments straight to C (caller guarantees slab capacity);
//           otherwise stage via smem with (gr<M, gc<N) guards + optional bias.
#define BM 128
#define BN 64
#define BKK 16
#define LDS 20            // BKK + 4
#define AOFF_LO   (BM*LDS)                 // 2560
#define BOFF_HI   (2*BM*LDS)               // 5120
#define BOFF_LO   (2*BM*LDS + BN*LDS)      // 6400
#define LOADSZ    (2*BM*LDS + 2*BN*LDS)    // 7680
#define EPISZ     (BM*BN)                  // 8192
#define SMEMSZ    ((LOADSZ > EPISZ) ? LOADSZ : EPISZ)

template<bool BROW, bool EXPA, bool DIRECT>
__device__ __forceinline__ void gemm_core(
    const float* __restrict__ A, int lda,
    const float* __restrict__ B, int ldb,
    float* __restrict__ C, int ldc,
    int M, int N, int K, float scale,
    const float* __restrict__ rinv,
    const float* __restrict__ bias,
    int m0, int n0)
{
    __shared__ __align__(16) float smem[SMEMSZ];

    const int tid  = threadIdx.x;          // 256 threads
    const int warp = tid >> 5;
    const int wm0 = (warp & 3) * 32;       // 4 warps along M
    const int wn0 = (warp >> 2) * 32;      // 2 warps along N

    wmma::fragment<wmma::accumulator, 16, 16, 8, float> acc[2][2];
    #pragma unroll
    for (int i = 0; i < 2; i++)
        #pragma unroll
        for (int j = 0; j < 2; j++) wmma::fill_fragment(acc[i][j], 0.f);

    for (int k0 = 0; k0 < K; k0 += BKK) {
        // ---- A tile: 128x16, split hi/lo at store ----
        #pragma unroll
        for (int ii = 0; ii < 2; ii++) {
            int i = tid + ii * 256;                 // 512 float4 slots
            int r = i >> 2, c4 = (i & 3) * 4;
            int gr = m0 + r, gk = k0 + c4;
            float4 v = make_float4(0.f, 0.f, 0.f, 0.f);
            bool rowok = (gr < M);
            if (rowok && gk + 3 < K) {
                v = *(const float4*)(A + (size_t)gr * lda + gk);
            } else if (rowok) {
                if (gk     < K) v.x = A[(size_t)gr * lda + gk];
                if (gk + 1 < K) v.y = A[(size_t)gr * lda + gk + 1];
                if (gk + 2 < K) v.z = A[(size_t)gr * lda + gk + 2];
                if (gk + 3 < K) v.w = A[(size_t)gr * lda + gk + 3];
            }
            if (EXPA) {
                float ri = rowok ? rinv[gr] : 0.f;
                v.x = (rowok && gk     < K) ? expf(v.x) * ri : 0.f;
                v.y = (rowok && gk + 1 < K) ? expf(v.y) * ri : 0.f;
                v.z = (rowok && gk + 2 < K) ? expf(v.z) * ri : 0.f;
                v.w = (rowok && gk + 3 < K) ? expf(v.w) * ri : 0.f;
            }
            float hx = wmma::__float_to_tf32(v.x);
            float hy = wmma::__float_to_tf32(v.y);
            float hz = wmma::__float_to_tf32(v.z);
            float hw = wmma::__float_to_tf32(v.w);
            *(float4*)&smem[r * LDS + c4] =
                make_float4(hx, hy, hz, hw);
            *(float4*)&smem[AOFF_LO + r * LDS + c4] =
                make_float4(wmma::__float_to_tf32(v.x - hx), wmma::__float_to_tf32(v.y - hy),
                            wmma::__float_to_tf32(v.z - hz), wmma::__float_to_tf32(v.w - hw));
        }
        // ---- B tile into [n][k] hi/lo ----
        if (!BROW) {
            // 64x16 row-major [n][k]: 256 float4 slots
            int i = tid;
            int r = i >> 2, c4 = (i & 3) * 4;
            int gn = n0 + r, gk = k0 + c4;
            float4 v = make_float4(0.f, 0.f, 0.f, 0.f);
            if (gn < N && gk + 3 < K) {
                v = *(const float4*)(B + (size_t)gn * ldb + gk);
            } else if (gn < N) {
                if (gk     < K) v.x = B[(size_t)gn * ldb + gk];
                if (gk + 1 < K) v.y = B[(size_t)gn * ldb + gk + 1];
                if (gk + 2 < K) v.z = B[(size_t)gn * ldb + gk + 2];
                if (gk + 3 < K) v.w = B[(size_t)gn * ldb + gk + 3];
            }
            float hx = wmma::__float_to_tf32(v.x);
            float hy = wmma::__float_to_tf32(v.y);
            float hz = wmma::__float_to_tf32(v.z);
            float hw = wmma::__float_to_tf32(v.w);
            *(float4*)&smem[BOFF_HI + r * LDS + c4] = make_float4(hx, hy, hz, hw);
            *(float4*)&smem[BOFF_LO + r * LDS + c4] =
                make_float4(wmma::__float_to_tf32(v.x - hx), wmma::__float_to_tf32(v.y - hy),
                            wmma::__float_to_tf32(v.z - hz), wmma::__float_to_tf32(v.w - hw));
        } else {
            // B [K,N]: 16 rows x 64 cols = 256 float4 slots, transpose to [n][k]
            int i = tid;
            int kr = i >> 4, c4 = (i & 15) * 4;
            int gk = k0 + kr, gn = n0 + c4;
            float4 v = make_float4(0.f, 0.f, 0.f, 0.f);
            if (gk < K && gn + 3 < N) {
                v = *(const float4*)(B + (size_t)gk * ldb + gn);
            } else if (gk < K) {
                if (gn     < N) v.x = B[(size_t)gk * ldb + gn];
                if (gn + 1 < N) v.y = B[(size_t)gk * ldb + gn + 1];
                if (gn + 2 < N) v.z = B[(size_t)gk * ldb + gn + 2];
                if (gn + 3 < N) v.w = B[(size_t)gk * ldb + gn + 3];
            }
            float h;
            h = wmma::__float_to_tf32(v.x);
            smem[BOFF_HI + (c4 + 0) * LDS + kr] = h;
            smem[BOFF_LO + (c4 + 0) * LDS + kr] = wmma::__float_to_tf32(v.x - h);
            h = wmma::__float_to_tf32(v.y);
            smem[BOFF_HI + (c4 + 1) * LDS + kr] = h;
            smem[BOFF_LO + (c4 + 1) * LDS + kr] = wmma::__float_to_tf32(v.y - h);
            h = wmma::__float_to_tf32(v.z);
            smem[BOFF_HI + (c4 + 2) * LDS + kr] = h;
            smem[BOFF_LO + (c4 + 2) * LDS + kr] = wmma::__float_to_tf32(v.z - h);
            h = wmma::__float_to_tf32(v.w);
            smem[BOFF_HI + (c4 + 3) * LDS + kr] = h;
            smem[BOFF_LO + (c4 + 3) * LDS + kr] = wmma::__float_to_tf32(v.w - h);
        }
        __syncthreads();

        #pragma unroll
        for (int kk = 0; kk < BKK; kk += 8) {
            wmma::fragment<wmma::matrix_a, 16, 16, 8, wmma::precision::tf32, wmma::row_major> ah[2], al[2];
            wmma::fragment<wmma::matrix_b, 16, 16, 8, wmma::precision::tf32, wmma::col_major> bh[2], bl[2];
            #pragma unroll
            for (int i = 0; i < 2; i++) {
                wmma::load_matrix_sync(ah[i], &smem[(wm0 + i * 16) * LDS + kk], LDS);
                wmma::load_matrix_sync(al[i], &smem[AOFF_LO + (wm0 + i * 16) * LDS + kk], LDS);
            }
            #pragma unroll
            for (int j = 0; j < 2; j++) {
                wmma::load_matrix_sync(bh[j], &smem[BOFF_HI + (wn0 + j * 16) * LDS + kk], LDS);
                wmma::load_matrix_sync(bl[j], &smem[BOFF_LO + (wn0 + j * 16) * LDS + kk], LDS);
            }
            #pragma unroll
            for (int i = 0; i < 2; i++)
                #pragma unroll
                for (int j = 0; j < 2; j++) {
                    wmma::mma_sync(acc[i][j], ah[i], bh[j], acc[i][j]);
                    wmma::mma_sync(acc[i][j], al[i], bh[j], acc[i][j]);
                    wmma::mma_sync(acc[i][j], ah[i], bl[j], acc[i][j]);
                }
        }
        __syncthreads();
    }

    #pragma unroll
    for (int i = 0; i < 2; i++)
        #pragma unroll
        for (int j = 0; j < 2; j++) {
            #pragma unroll
            for (int e = 0; e < acc[i][j].num_elements; e++) acc[i][j].x[e] *= scale;
        }

    if (DIRECT) {
        #pragma unroll
        for (int i = 0; i < 2; i++)
            #pragma unroll
            for (int j = 0; j < 2; j++)
                wmma::store_matrix_sync(C + (size_t)(m0 + wm0 + i * 16) * ldc + (n0 + wn0 + j * 16),
                                        acc[i][j], ldc, wmma::mem_row_major);
    } else {
        #pragma unroll
        for (int i = 0; i < 2; i++)
            #pragma unroll
            for (int j = 0; j < 2; j++)
                wmma::store_matrix_sync(smem + (wm0 + i * 16) * BN + (wn0 + j * 16),
                                        acc[i][j], BN, wmma::mem_row_major);
        __syncthreads();
        #pragma unroll
        for (int ii = 0; ii < 32; ii++) {
            int idx = tid + ii * 256;
            int r = idx >> 6, c = idx & 63;
            int gr = m0 + r, gc = n0 + c;
            if (gr < M && gc < N)
                C[(size_t)gr * ldc + gc] = smem[idx] + (bias ? bias[gc] : 0.f);
        }
    }
}

// ---------------- GEMM wrappers ---------------------------------------------
__global__ __launch_bounds__(256, 2)
void k_gemm(const float* __restrict__ Aext, int Asel,
            const float* __restrict__ W, const float* __restrict__ bias,
            int Csel, int N, int K, int stage) {
    int M = NB * seqlen(stage);
    int m0 = blockIdx.y * BM;
    if (m0 >= M) return;
    int n0 = blockIdx.x * BN;
    const float* A = (Asel == 0) ? Aext : (Asel == 1 ? d_merged : d_AO);
    float* C = (Csel == 0) ? d_qkv : d_stage;
    gemm_core<false, false, false>(A, K, W, K, C, N, M, N, K, 1.f, nullptr, bias, m0, n0);
}

__global__ __launch_bounds__(256, 2)
void k_scores(int stage) {
    int L = seqlen(stage);
    int m0 = blockIdx.y * BM, n0 = blockIdx.x * BN;
    if (m0 >= L || n0 >= L) return;
    int bh = blockIdx.z;
    int b = bh / NH, h = bh % NH;
    const float* Q  = d_qkv + (size_t)b * L * NQKV + h * NHD;
    const float* Kp = Q + ND;
    float* S = d_S + (size_t)bh * NT * NT;
    // direct store: tile overhang stays inside the NT x NT slab
    gemm_core<false, false, true>(Q, NQKV, Kp, NQKV, S, NT, L, L, NHD, 0.125f, nullptr, nullptr, m0, n0);
}

__global__ __launch_bounds__(256, 2)
void k_av(int stage) {
    int L = seqlen(stage);
    int m0 = blockIdx.y * BM;
    if (m0 >= L) return;
    int bh = blockIdx.z;
    int b = bh / NH, h = bh % NH;
    const float* S = d_S + (size_t)bh * NT * NT;
    const float* V = d_qkv + (size_t)b * L * NQKV + 2 * ND + h * NHD;
    float* C = d_AO + (size_t)b * L * ND + h * NHD;
    gemm_core<true, true, false>(S, NT, V, NQKV, C, ND, L, NHD, L, 1.f,
                                 d_rinv + (size_t)bh * NT, nullptr, m0, 0);
}

// ------- fused row stats (sum of exp) + head-mean output --------------------
__global__ __launch_bounds__(256)
void k_rowstat(int stage, float* __restrict__ out) {
    int L = seqlen(stage);
    int q = blockIdx.x;
    if (q >= L) return;
    int b = blockIdx.y;
    int t = threadIdx.x;

    float e[NH][8];
    float rv[NH];
    __shared__ float red[256];

    #pragma unroll
    for (int h = 0; h < NH; h++) {
        const float* row = d_S + ((size_t)(b * NH + h) * NT + q) * NT;
        float s = 0.f;
        #pragma unroll
        for (int c = 0; c < 8; c++) {
            int k = t + (c << 8);
            float x = (k < L) ? expf(row[k]) : 0.f;
            e[h][c] = x;
            s += x;
        }
        red[t] = s; __syncthreads();
        #pragma unroll
        for (int st = 128; st > 0; st >>= 1) { if (t < st) red[t] += red[t + st]; __syncthreads(); }
        rv[h] = 1.f / red[0];
        __syncthreads();
    }

    float* dst = out + g_off[stage] + ((size_t)b * L + q) * L;
    #pragma unroll
    for (int c = 0; c < 8; c++) {
        int k = t + (c << 8);
        if (k < L) {
            float s = 0.f;
            #pragma unroll
            for (int h = 0; h < NH; h++) s += e[h][c] * rv[h];
            dst[k] = 0.125f * s;
        }
    }
    if (t == 0) {
        #pragma unroll
        for (int h = 0; h < NH; h++) d_rinv[(size_t)(b * NH + h) * NT + q] = rv[h];
    }
}

// ---------------- segment mean merge: d_stage -> d_merged -------------------
__global__ __launch_bounds__(256)
void merge_kernel(int which) {
    int m   = (which == 1) ? g_m1 : g_m2;
    int Tin = (which == 1) ? NT : g_m1;
    const int* start = (which == 1) ? g_start1 : g_start2;
    int j = blockIdx.x + 1;
    if (j > m) return;
    int b = blockIdx.y;
    int s0 = start[j], s1 = start[j + 1];
    float cnt = (float)(s1 - s0);
    const float* in = d_stage + ((size_t)b * Tin) * ND;
    float* outp = d_merged + ((size_t)(b * m + (j - 1))) * ND;
    for (int d = threadIdx.x; d < ND; d += 256) {
        float s = 0.f;
        for (int t = s0; t < s1; t++) s += in[(size_t)t * ND + d];
        outp[d] = s / (cnt + 1e-10f);
    }
}

// ---------------- expand glob_out to selected tokens -> d_out[0..] ----------
__global__ __launch_bounds__(256)
void expand_kernel(float* __restrict__ out) {
    int i = blockIdx.x;
    if (i >= g_ntok) return;
    int b = blockIdx.y;
    int t = g_tokmap[i];
    int gsrc = g_tokg[t] - 1;
    int m2 = g_m2;
    const float* src = d_stage + ((size_t)(b * m2 + gsrc)) * ND;
    float* dst = out + ((size_t)b * g_ntok + i) * ND;
    for (int d = threadIdx.x; d < ND; d += 256) dst[d] = src[d];
}

// ---------------- launch ----------------------------------------------------
extern "C" void kernel_launch(void* const* d_in, const int* in_sizes, int n_in,
                              void* d_out, int out_size) {
    (void)in_sizes; (void)n_in; (void)out_size;
    const float* x    = (const float*)d_in[0];
    const float* cWi  = (const float*)d_in[1];
    const float* cbi  = (const float*)d_in[2];
    const float* cWo  = (const float*)d_in[3];
    const float* cbo  = (const float*)d_in[4];
    const float* bWi  = (const float*)d_in[5];
    const float* bbi  = (const float*)d_in[6];
    const float* bWo  = (const float*)d_in[7];
    const float* bbo  = (const float*)d_in[8];
    const float* gWi  = (const float*)d_in[9];
    const float* gbi  = (const float*)d_in[10];
    const float* gWo  = (const float*)d_in[11];
    const float* gbo  = (const float*)d_in[12];
    const float* mw   = (const float*)d_in[13];
    const float* mb   = (const float*)d_in[14];
    const float* gmw  = (const float*)d_in[15];
    const float* gmb  = (const float*)d_in[16];
    float* out = (float*)d_out;

    setup_kernel<<<1, 1>>>(mw, mb, gmw, gmb);

    const dim3 gQKV(NQKV / BN, MAXROWS / BM);     // (24, 32)
    const dim3 gOUT(ND / BN, MAXROWS / BM);       // (8, 32)
    const dim3 gSC(NT / BN, NT / BM, NB * NH);    // (32, 16, 16)
    const dim3 gAV(1, NT / BM, NB * NH);          // (1, 16, 16)
    const dim3 gRS(NT, NB);

    for (int stage = 0; stage < 3; stage++) {
        const float* Wi = stage == 0 ? cWi : (stage == 1 ? bWi : gWi);
        const float* bi = stage == 0 ? cbi : (stage == 1 ? bbi : gbi);
        const float* Wo = stage == 0 ? cWo : (stage == 1 ? bWo : gWo);
        const float* bo = stage == 0 ? cbo : (stage == 1 ? bbo : gbo);
        int Asel = (stage == 0) ? 0 : 1;

        k_gemm<<<gQKV, 256>>>(x, Asel, Wi, bi, 0, NQKV, ND, stage);
        k_scores<<<gSC, 256>>>(stage);
        k_rowstat<<<gRS, 256>>>(stage, out);
        k_av<<<gAV, 256>>>(stage);
        k_gemm<<<gOUT, 256>>>(nullptr, 2, Wo, bo, 1, ND, ND, stage);

        if (stage == 0) merge_kernel<<<dim3(NT, NB), 256>>>(1);
        if (stage == 1) merge_kernel<<<dim3(NT, NB), 256>>>(2);
    }

    expand_kernel<<<dim3(NT, NB), 256>>>(out);
}